// round 7
// baseline (speedup 1.0000x reference)
#include <cuda_runtime.h>
#include <cstdint>

// ============================================================================
// Problem constants
// ============================================================================
static constexpr int N_ROWS = 16384;   // N nodes
static constexpr int F_DIM  = 64;      // features
static constexpr int U_DIM  = 64;      // output units

// Transposed expmap output: g_xT[n][k] = x_proj[k][n], [64, 16384] fp32 (tf32-rounded)
__device__ float g_xT[(size_t)F_DIM * N_ROWS];

// ============================================================================
// Helpers — baseline PTX only (sm_103, NO 'a'-suffix features)
// ============================================================================
__device__ __forceinline__ uint32_t smem_u32(const void* p) {
    uint32_t a;
    asm("{ .reg .u64 t; cvta.to.shared.u64 t, %1; cvt.u32.u64 %0, t; }"
        : "=r"(a) : "l"(p));
    return a;
}

// SW128 swizzle valid for 128-byte rows: XOR bits[6:4] with row&7
#define SW128(x) ((x) ^ (((x) >> 3) & 0x70))

__device__ __forceinline__ void cp_async16(uint32_t saddr, const void* gptr) {
    asm volatile("cp.async.cg.shared.global [%0], [%1], 16;"
                 :: "r"(saddr), "l"(gptr) : "memory");
}
#define CP_COMMIT() asm volatile("cp.async.commit_group;" ::: "memory")
template <int Ngrp>
__device__ __forceinline__ void cp_wait() {
    asm volatile("cp.async.wait_group %0;" :: "n"(Ngrp) : "memory");
}

__device__ __forceinline__ void ldsm_x4(uint32_t r[4], uint32_t addr) {
    asm volatile("ldmatrix.sync.aligned.m8n8.x4.shared.b16 {%0,%1,%2,%3}, [%4];"
                 : "=r"(r[0]), "=r"(r[1]), "=r"(r[2]), "=r"(r[3]) : "r"(addr));
}

__device__ __forceinline__ uint32_t cvt_rna_tf32(uint32_t x) {
    uint32_t y;
    asm("cvt.rna.tf32.f32 %0, %1;" : "=r"(y) : "f"(__uint_as_float(x)));
    return y;
}

// D += A*B, m16n8k8 tf32, fp32 accumulate (sm_80+ baseline ISA)
__device__ __forceinline__ void mma_tf32(float d[4], const uint32_t a[4],
                                         uint32_t b0, uint32_t b1) {
    asm volatile(
        "mma.sync.aligned.m16n8k8.row.col.f32.tf32.tf32.f32 "
        "{%0,%1,%2,%3}, {%4,%5,%6,%7}, {%8,%9}, {%0,%1,%2,%3};"
        : "+f"(d[0]), "+f"(d[1]), "+f"(d[2]), "+f"(d[3])
        : "r"(a[0]), "r"(a[1]), "r"(a[2]), "r"(a[3]), "r"(b0), "r"(b1));
}

// ============================================================================
// Kernel 1: Poincare expmap + transpose (x[16384,64] -> g_xT[64,16384])
// ============================================================================
__global__ __launch_bounds__(256) void expmap_transpose(const float* __restrict__ x) {
    __shared__ float tile[64][65];
    __shared__ float scl[64];
    const int k0 = blockIdx.x * 64;
    const int t = threadIdx.x;

#pragma unroll
    for (int i = 0; i < 16; i++) {
        int idx = t + i * 256;
        int r = idx >> 6, c = idx & 63;
        tile[r][c] = x[(size_t)(k0 + r) * F_DIM + c];
    }
    __syncthreads();

    if (t < 64) {
        float s = 0.0f;
#pragma unroll
        for (int c = 0; c < 64; c++) { float v = tile[t][c]; s += v * v; }
        float n = fminf(sqrtf(s), 10.0f);
        scl[t] = tanhf(n) / (n + 1e-8f);
    }
    __syncthreads();

    const int kl = t & 63;
    const int ng = t >> 6;  // 4 groups of 64 threads
#pragma unroll
    for (int nn = ng; nn < 64; nn += 4) {
        float v = tile[kl][nn] * scl[kl];
        uint32_t u;
        asm("cvt.rna.tf32.f32 %0, %1;" : "=r"(u) : "f"(v));  // pre-round B: no bias
        g_xT[(size_t)nn * N_ROWS + k0 + kl] = __uint_as_float(u);
    }
}

// ============================================================================
// Kernel 2: pipelined tf32 mma.sync GEMM (support = adj @ x_proj)
//           + fused logmap + dense(kernel) + bias epilogue
// 512 threads, 16 warps: wm(8) x wn(2), warp tile m16 x n32
// ============================================================================
static constexpr int STAGES = 6;
static constexpr int KC     = 32;                // K per stage (128B rows)
static constexpr int ITERS  = N_ROWS / KC;       // 512

static constexpr int SMEM_BIAS   = 128;          // 256B
static constexpr int SMEM_KER    = 512;          // 16KB, [k][u] row-major
static constexpr int SMEM_STAGE0 = 17408;        // 1024-aligned
static constexpr int STAGE_BYTES = 24576;        // A 16KB + B 8KB
static constexpr int A_OFF       = 0;
static constexpr int B_OFF       = 16384;
static constexpr int SMEM_TOTAL  = SMEM_STAGE0 + STAGES * STAGE_BYTES;  // 164864
static constexpr int SMEM_C      = SMEM_STAGE0;  // C tile reuses stage ring
static constexpr int C_STRIDE    = 68;           // floats per row (16B-aligned rows)

__global__ __launch_bounds__(512, 1) void hgc_gemm(
    const float* __restrict__ adj,
    const float* __restrict__ ker,
    const float* __restrict__ bias,
    float* __restrict__ out)
{
    extern __shared__ char smem[];
    const uint32_t sb = smem_u32(smem);
    const int tid  = threadIdx.x;
    const int lane = tid & 31;
    const int wid  = tid >> 5;
    const int wm   = wid >> 1;      // 8 warps along M (16 rows each)
    const int wn   = wid & 1;       // 2 warps along N (32 cols each)
    const int m0   = blockIdx.x * 128;

    // stage kernel matrix + bias into smem
    float* kers = (float*)(smem + SMEM_KER);
#pragma unroll
    for (int i = 0; i < 8; i++) kers[tid + i * 512] = ker[tid + i * 512];
    if (tid < 64) ((float*)(smem + SMEM_BIAS))[tid] = bias[tid];
    __syncthreads();

    // ---- cp.async source/dest mapping: 1536 16B chunks / 512 threads = 3 each
    const char* gp[3];
    uint32_t so[3];
#pragma unroll
    for (int j = 0; j < 3; j++) {
        int c = tid + j * 512;
        if (c < 1024) {                       // A: 128 rows x 8 chunks
            int r = c >> 3, cc = c & 7;
            gp[j] = (const char*)(adj + (size_t)(m0 + r) * N_ROWS) + cc * 16;
            so[j] = A_OFF + SW128(r * 128 + cc * 16);
        } else {                              // B: 64 rows x 8 chunks
            int c2 = c - 1024;
            int n = c2 >> 3, cc = c2 & 7;
            gp[j] = (const char*)(g_xT + (size_t)n * N_ROWS) + cc * 16;
            so[j] = B_OFF + SW128(n * 128 + cc * 16);
        }
    }

    // ---- ldmatrix swizzled offsets, fully precomputed (per lane, per k8)
    const int rr = lane & 7, mi = lane >> 3;
    uint32_t aOff[4], bOff[2][4];
    {
        // A m16xk8 frag: row = wm*16 + (mi&1)*8 + rr, K half by (mi>>1)
        const int ar = wm * 16 + (mi & 1) * 8 + rr;
        const int aKhalf = (mi >> 1) * 16;
        // B k8xn8 x4 frag pair: n = wn*32 + g*16 + (mi>>1)*8 + rr, K half by (mi&1)
        const int bKhalf = (mi & 1) * 16;
#pragma unroll
        for (int k8 = 0; k8 < 4; k8++) {
            aOff[k8] = A_OFF + SW128(ar * 128 + k8 * 32 + aKhalf);
#pragma unroll
            for (int g = 0; g < 2; g++) {
                const int bn = wn * 32 + g * 16 + (mi >> 1) * 8 + rr;
                bOff[g][k8] = B_OFF + SW128(bn * 128 + k8 * 32 + bKhalf);
            }
        }
    }

    float acc[4][4];
#pragma unroll
    for (int nt = 0; nt < 4; nt++)
#pragma unroll
        for (int q = 0; q < 4; q++) acc[nt][q] = 0.0f;

    // ---- prologue: fill stages 0..4
#pragma unroll 1
    for (int s = 0; s < STAGES - 1; s++) {
        const uint32_t stb = sb + SMEM_STAGE0 + s * STAGE_BYTES;
        const size_t goff = (size_t)s * 128;  // KC*4 bytes along K
#pragma unroll
        for (int j = 0; j < 3; j++) cp_async16(stb + so[j], gp[j] + goff);
        CP_COMMIT();
    }

    // ---- main loop
#pragma unroll 1
    for (int i = 0; i < ITERS; i++) {
        cp_wait<STAGES - 2>();     // stage i landed
        __syncthreads();           // visible to all; stage (i+5)%6 free to refill

        const int nx = i + STAGES - 1;
        if (nx < ITERS) {
            const uint32_t stb = sb + SMEM_STAGE0 + (nx % STAGES) * STAGE_BYTES;
            const size_t goff = (size_t)nx * 128;
#pragma unroll
            for (int j = 0; j < 3; j++) cp_async16(stb + so[j], gp[j] + goff);
        }
        CP_COMMIT();               // keep group count uniform

        const uint32_t st = sb + SMEM_STAGE0 + (i % STAGES) * STAGE_BYTES;
#pragma unroll
        for (int k8 = 0; k8 < 4; k8++) {
            uint32_t a[4], b[2][4];
            ldsm_x4(a, st + aOff[k8]);
            ldsm_x4(b[0], st + bOff[0][k8]);
            ldsm_x4(b[1], st + bOff[1][k8]);
#pragma unroll
            for (int q = 0; q < 4; q++) a[q] = cvt_rna_tf32(a[q]);
#pragma unroll
            for (int nt = 0; nt < 4; nt++)
                mma_tf32(acc[nt], a, b[nt >> 1][(nt & 1) * 2],
                         b[nt >> 1][(nt & 1) * 2 + 1]);
        }
    }
    __syncthreads();  // all compute done; stage ring reusable as C tile

    // ---- spill accumulators to smem C [128][C_STRIDE]
    float* Csm = (float*)(smem + SMEM_C);
    {
        const int R0 = wm * 16 + (lane >> 2);
#pragma unroll
        for (int nt = 0; nt < 4; nt++) {
            const int C0 = wn * 32 + nt * 8 + (lane & 3) * 2;
            Csm[R0 * C_STRIDE + C0]           = acc[nt][0];
            Csm[R0 * C_STRIDE + C0 + 1]       = acc[nt][1];
            Csm[(R0 + 8) * C_STRIDE + C0]     = acc[nt][2];
            Csm[(R0 + 8) * C_STRIDE + C0 + 1] = acc[nt][3];
        }
    }
    __syncthreads();

    // ---- fused epilogue: logmap + dense + bias (one thread per output row)
    if (tid < 128) {
        float y[64];
        const float4* crow = (const float4*)(Csm + tid * C_STRIDE);
#pragma unroll
        for (int j = 0; j < 16; j++) ((float4*)y)[j] = crow[j];

        float s2 = 0.0f;
#pragma unroll
        for (int j = 0; j < 64; j++) s2 += y[j] * y[j];
        float nrm = sqrtf(s2);
        float nc = fminf(nrm, 0.999f);
        float sc = atanhf(nc) / (nc + 1e-8f);
#pragma unroll
        for (int j = 0; j < 64; j++) y[j] *= sc;

        const float4* kf = (const float4*)(smem + SMEM_KER);   // [k][u]
        const float* bs = (const float*)(smem + SMEM_BIAS);
        float4* outv = (float4*)(out + (size_t)(m0 + tid) * U_DIM);
#pragma unroll 1
        for (int u0 = 0; u0 < 16; u0++) {
            float4 a4 = make_float4(bs[u0 * 4], bs[u0 * 4 + 1],
                                    bs[u0 * 4 + 2], bs[u0 * 4 + 3]);
#pragma unroll
            for (int k = 0; k < 64; k++) {
                float4 kv = kf[k * 16 + u0];   // broadcast LDS128
                a4.x += y[k] * kv.x; a4.y += y[k] * kv.y;
                a4.z += y[k] * kv.z; a4.w += y[k] * kv.w;
            }
            outv[u0] = a4;
        }
    }
}

// ============================================================================
// Launch
// ============================================================================
extern "C" void kernel_launch(void* const* d_in, const int* in_sizes, int n_in,
                              void* d_out, int out_size) {
    const float *x = nullptr, *adj = nullptr, *ker = nullptr, *bias = nullptr;
    for (int i = 0; i < n_in; i++) {
        long sz = in_sizes[i];
        if (sz == (long)N_ROWS * N_ROWS)      adj  = (const float*)d_in[i];
        else if (sz == (long)N_ROWS * F_DIM)  x    = (const float*)d_in[i];
        else if (sz == (long)F_DIM * U_DIM)   ker  = (const float*)d_in[i];
        else if (sz == (long)U_DIM)           bias = (const float*)d_in[i];
    }
    float* out = (float*)d_out;

    cudaFuncSetAttribute(hgc_gemm, cudaFuncAttributeMaxDynamicSharedMemorySize, SMEM_TOTAL);

    expmap_transpose<<<N_ROWS / 64, 256>>>(x);
    hgc_gemm<<<N_ROWS / 128, 512, SMEM_TOTAL>>>(adj, ker, bias, out);
}

// round 9
// speedup vs baseline: 1.1820x; 1.1820x over previous
#include <cuda_runtime.h>
#include <cstdint>

// ============================================================================
// Problem constants
// ============================================================================
static constexpr int N_ROWS = 16384;   // N nodes
static constexpr int F_DIM  = 64;      // features
static constexpr int U_DIM  = 64;      // output units

// Transposed expmap output: g_xT[n][k] = x_proj[k][n], [64, 16384] fp32 (tf32-rounded)
__device__ float g_xT[(size_t)F_DIM * N_ROWS];

// ============================================================================
// Helpers — baseline PTX only (sm_103, NO 'a'-suffix features)
// ============================================================================
__device__ __forceinline__ uint32_t smem_u32(const void* p) {
    uint32_t a;
    asm("{ .reg .u64 t; cvta.to.shared.u64 t, %1; cvt.u32.u64 %0, t; }"
        : "=r"(a) : "l"(p));
    return a;
}

// SW128 swizzle valid for 128-byte rows: XOR bits[6:4] with row&7
#define SW128(x) ((x) ^ (((x) >> 3) & 0x70))

__device__ __forceinline__ void cp_async16(uint32_t saddr, const void* gptr) {
    asm volatile("cp.async.cg.shared.global [%0], [%1], 16;"
                 :: "r"(saddr), "l"(gptr) : "memory");
}
#define CP_COMMIT() asm volatile("cp.async.commit_group;" ::: "memory")
template <int Ngrp>
__device__ __forceinline__ void cp_wait() {
    asm volatile("cp.async.wait_group %0;" :: "n"(Ngrp) : "memory");
}

__device__ __forceinline__ void ldsm_x4(uint32_t r[4], uint32_t addr) {
    asm volatile("ldmatrix.sync.aligned.m8n8.x4.shared.b16 {%0,%1,%2,%3}, [%4];"
                 : "=r"(r[0]), "=r"(r[1]), "=r"(r[2]), "=r"(r[3]) : "r"(addr));
}

__device__ __forceinline__ uint32_t cvt_rna_tf32(uint32_t x) {
    uint32_t y;
    asm("cvt.rna.tf32.f32 %0, %1;" : "=r"(y) : "f"(__uint_as_float(x)));
    return y;
}

// D += A*B, m16n8k8 tf32, fp32 accumulate (sm_80+ baseline ISA)
__device__ __forceinline__ void mma_tf32(float d[4], const uint32_t a[4],
                                         uint32_t b0, uint32_t b1) {
    asm volatile(
        "mma.sync.aligned.m16n8k8.row.col.f32.tf32.tf32.f32 "
        "{%0,%1,%2,%3}, {%4,%5,%6,%7}, {%8,%9}, {%0,%1,%2,%3};"
        : "+f"(d[0]), "+f"(d[1]), "+f"(d[2]), "+f"(d[3])
        : "r"(a[0]), "r"(a[1]), "r"(a[2]), "r"(a[3]), "r"(b0), "r"(b1));
}

// ============================================================================
// Kernel 1: Poincare expmap + transpose (x[16384,64] -> g_xT[64,16384])
// ============================================================================
__global__ __launch_bounds__(256) void expmap_transpose(const float* __restrict__ x) {
    __shared__ float tile[64][65];
    __shared__ float scl[64];
    const int k0 = blockIdx.x * 64;
    const int t = threadIdx.x;

#pragma unroll
    for (int i = 0; i < 16; i++) {
        int idx = t + i * 256;
        int r = idx >> 6, c = idx & 63;
        tile[r][c] = x[(size_t)(k0 + r) * F_DIM + c];
    }
    __syncthreads();

    if (t < 64) {
        float s = 0.0f;
#pragma unroll
        for (int c = 0; c < 64; c++) { float v = tile[t][c]; s += v * v; }
        float n = fminf(sqrtf(s), 10.0f);
        scl[t] = tanhf(n) / (n + 1e-8f);
    }
    __syncthreads();

    const int kl = t & 63;
    const int ng = t >> 6;  // 4 groups of 64 threads
#pragma unroll
    for (int nn = ng; nn < 64; nn += 4) {
        float v = tile[kl][nn] * scl[kl];
        uint32_t u;
        asm("cvt.rna.tf32.f32 %0, %1;" : "=r"(u) : "f"(v));  // pre-round B: no bias
        g_xT[(size_t)nn * N_ROWS + k0 + kl] = __uint_as_float(u);
    }
}

// ============================================================================
// Kernel 2: pipelined tf32 mma.sync GEMM (support = adj @ x_proj)
//           + fused logmap + dense(kernel) + bias epilogue
// 256 threads, 8 warps: wm(4) x wn(2), warp tile m32 x n32 (R6 layout)
// KC=64 per stage (two 128B-row SW128 blocks), 3 stages, 256 barriers total.
// Software-pipelined k8 loop: ldmatrix k8+1 overlaps mma k8.
// ============================================================================
static constexpr int STAGES = 3;
static constexpr int KC     = 64;                // K per stage = 2 x 128B blocks
static constexpr int ITERS  = N_ROWS / KC;       // 256

static constexpr int SMEM_BIAS   = 128;          // 256B
static constexpr int SMEM_KER    = 512;          // 16KB, [k][u] row-major
static constexpr int SMEM_STAGE0 = 17408;        // 1024-aligned
static constexpr int STAGE_BYTES = 49152;        // A 32KB + B 16KB
static constexpr int A_OFF       = 0;            // A: blocks of 16KB per K-half
static constexpr int B_OFF       = 32768;        // B: blocks of 8KB per K-half
static constexpr int SMEM_TOTAL  = SMEM_STAGE0 + STAGES * STAGE_BYTES;  // 164864
static constexpr int SMEM_C      = SMEM_STAGE0;  // C tile reuses stage ring
static constexpr int C_STRIDE    = 68;           // floats per row (16B-aligned rows)

__global__ __launch_bounds__(256, 1) void hgc_gemm(
    const float* __restrict__ adj,
    const float* __restrict__ ker,
    const float* __restrict__ bias,
    float* __restrict__ out)
{
    extern __shared__ char smem[];
    const uint32_t sb = smem_u32(smem);
    const int tid  = threadIdx.x;
    const int lane = tid & 31;
    const int wid  = tid >> 5;
    const int wm   = wid & 3;       // 4 warps along M (32 rows each)
    const int wn   = wid >> 2;      // 2 warps along N (32 cols each)
    const int m0   = blockIdx.x * 128;

    // stage kernel matrix + bias into smem
    float* kers = (float*)(smem + SMEM_KER);
#pragma unroll
    for (int i = 0; i < 16; i++) kers[tid + i * 256] = ker[tid + i * 256];
    if (tid < 64) ((float*)(smem + SMEM_BIAS))[tid] = bias[tid];
    __syncthreads();

    // ---- cp.async mapping: 3072 16B chunks / 256 threads = 12 each
    // A: 128 rows x 16 chunks (256B of K), K-half h=cc>>3 selects 16KB block
    // B: 64 rows x 16 chunks, K-half selects 8KB block
    const char* gp[12];
    uint32_t so[12];
#pragma unroll
    for (int j = 0; j < 12; j++) {
        int c = tid + j * 256;
        if (c < 2048) {
            int r = c >> 4, cc = c & 15;
            gp[j] = (const char*)(adj + (size_t)(m0 + r) * N_ROWS) + cc * 16;
            so[j] = A_OFF + (cc >> 3) * 16384 + SW128(r * 128 + (cc & 7) * 16);
        } else {
            int c2 = c - 2048;
            int n = c2 >> 4, cc = c2 & 15;
            gp[j] = (const char*)(g_xT + (size_t)n * N_ROWS) + cc * 16;
            so[j] = B_OFF + (cc >> 3) * 8192 + SW128(n * 128 + (cc & 7) * 16);
        }
    }

    // ---- ldmatrix swizzled offsets, fully precomputed (per lane, per k8 0..7)
    const int rr = lane & 7, mi = lane >> 3;
    uint32_t aOff[2][8], bOff[2][8];
    {
        const int aKhalf = (mi >> 1) * 16;
        const int bKhalf = (mi & 1) * 16;
#pragma unroll
        for (int k8 = 0; k8 < 8; k8++) {
            const int hA = (k8 >> 2) * 16384, hB = (k8 >> 2) * 8192;
            const int kin = (k8 & 3) * 32;
#pragma unroll
            for (int mt = 0; mt < 2; mt++) {
                const int ar = wm * 32 + mt * 16 + (mi & 1) * 8 + rr;
                aOff[mt][k8] = A_OFF + hA + SW128(ar * 128 + kin + aKhalf);
            }
#pragma unroll
            for (int g = 0; g < 2; g++) {
                const int bn = wn * 32 + g * 16 + (mi >> 1) * 8 + rr;
                bOff[g][k8] = B_OFF + hB + SW128(bn * 128 + kin + bKhalf);
            }
        }
    }

    float acc[2][4][4];
#pragma unroll
    for (int mt = 0; mt < 2; mt++)
#pragma unroll
        for (int nt = 0; nt < 4; nt++)
#pragma unroll
            for (int q = 0; q < 4; q++) acc[mt][nt][q] = 0.0f;

    // ---- prologue: fill stages 0..1
#pragma unroll 1
    for (int s = 0; s < STAGES - 1; s++) {
        const uint32_t stb = sb + SMEM_STAGE0 + s * STAGE_BYTES;
        const size_t goff = (size_t)s * 256;  // KC*4 bytes along K
#pragma unroll
        for (int j = 0; j < 12; j++) cp_async16(stb + so[j], gp[j] + goff);
        CP_COMMIT();
    }

    // ---- main loop (256 iterations, one barrier each)
#pragma unroll 1
    for (int i = 0; i < ITERS; i++) {
        cp_wait<STAGES - 2>();     // stage i landed
        __syncthreads();           // visible to all; slot (i+2)%3 free to refill

        const int nx = i + STAGES - 1;
        if (nx < ITERS) {
            const uint32_t stb = sb + SMEM_STAGE0 + (nx % STAGES) * STAGE_BYTES;
            const size_t goff = (size_t)nx * 256;
#pragma unroll
            for (int j = 0; j < 12; j++) cp_async16(stb + so[j], gp[j] + goff);
        }
        CP_COMMIT();               // keep group count uniform

        const uint32_t st = sb + SMEM_STAGE0 + (i % STAGES) * STAGE_BYTES;

        // software pipeline: double-buffered fragments
        uint32_t a[2][2][4], b[2][2][4];
        ldsm_x4(a[0][0], st + aOff[0][0]);
        ldsm_x4(a[0][1], st + aOff[1][0]);
        ldsm_x4(b[0][0], st + bOff[0][0]);
        ldsm_x4(b[0][1], st + bOff[1][0]);
#pragma unroll
        for (int k8 = 0; k8 < 8; k8++) {
            const int cur = k8 & 1, nxt = cur ^ 1;
            if (k8 < 7) {
                ldsm_x4(a[nxt][0], st + aOff[0][k8 + 1]);
                ldsm_x4(a[nxt][1], st + aOff[1][k8 + 1]);
                ldsm_x4(b[nxt][0], st + bOff[0][k8 + 1]);
                ldsm_x4(b[nxt][1], st + bOff[1][k8 + 1]);
            }
            uint32_t ar2[2][4];
#pragma unroll
            for (int mt = 0; mt < 2; mt++)
#pragma unroll
                for (int q = 0; q < 4; q++) ar2[mt][q] = cvt_rna_tf32(a[cur][mt][q]);
#pragma unroll
            for (int mt = 0; mt < 2; mt++)
#pragma unroll
                for (int nt = 0; nt < 4; nt++)
                    mma_tf32(acc[mt][nt], ar2[mt], b[cur][nt >> 1][(nt & 1) * 2],
                             b[cur][nt >> 1][(nt & 1) * 2 + 1]);
        }
    }
    __syncthreads();  // all compute done; stage ring reusable as C tile

    // ---- spill accumulators to smem C [128][C_STRIDE]
    float* Csm = (float*)(smem + SMEM_C);
#pragma unroll
    for (int mt = 0; mt < 2; mt++) {
        const int R0 = wm * 32 + mt * 16 + (lane >> 2);
#pragma unroll
        for (int nt = 0; nt < 4; nt++) {
            const int C0 = wn * 32 + nt * 8 + (lane & 3) * 2;
            Csm[R0 * C_STRIDE + C0]           = acc[mt][nt][0];
            Csm[R0 * C_STRIDE + C0 + 1]       = acc[mt][nt][1];
            Csm[(R0 + 8) * C_STRIDE + C0]     = acc[mt][nt][2];
            Csm[(R0 + 8) * C_STRIDE + C0 + 1] = acc[mt][nt][3];
        }
    }
    __syncthreads();

    // ---- fused epilogue: logmap + dense + bias (one thread per output row)
    if (tid < 128) {
        float y[64];
        const float4* crow = (const float4*)(Csm + tid * C_STRIDE);
#pragma unroll
        for (int j = 0; j < 16; j++) ((float4*)y)[j] = crow[j];

        float s2 = 0.0f;
#pragma unroll
        for (int j = 0; j < 64; j++) s2 += y[j] * y[j];
        float nrm = sqrtf(s2);
        float nc = fminf(nrm, 0.999f);
        float sc = atanhf(nc) / (nc + 1e-8f);
#pragma unroll
        for (int j = 0; j < 64; j++) y[j] *= sc;

        const float4* kf = (const float4*)(smem + SMEM_KER);   // [k][u]
        const float* bs = (const float*)(smem + SMEM_BIAS);
        float4* outv = (float4*)(out + (size_t)(m0 + tid) * U_DIM);
#pragma unroll 1
        for (int u0 = 0; u0 < 16; u0++) {
            float4 a4 = make_float4(bs[u0 * 4], bs[u0 * 4 + 1],
                                    bs[u0 * 4 + 2], bs[u0 * 4 + 3]);
#pragma unroll
            for (int k = 0; k < 64; k++) {
                float4 kv = kf[k * 16 + u0];   // broadcast LDS128
                a4.x += y[k] * kv.x; a4.y += y[k] * kv.y;
                a4.z += y[k] * kv.z; a4.w += y[k] * kv.w;
            }
            outv[u0] = a4;
        }
    }
}

// ============================================================================
// Launch
// ============================================================================
extern "C" void kernel_launch(void* const* d_in, const int* in_sizes, int n_in,
                              void* d_out, int out_size) {
    const float *x = nullptr, *adj = nullptr, *ker = nullptr, *bias = nullptr;
    for (int i = 0; i < n_in; i++) {
        long sz = in_sizes[i];
        if (sz == (long)N_ROWS * N_ROWS)      adj  = (const float*)d_in[i];
        else if (sz == (long)N_ROWS * F_DIM)  x    = (const float*)d_in[i];
        else if (sz == (long)F_DIM * U_DIM)   ker  = (const float*)d_in[i];
        else if (sz == (long)U_DIM)           bias = (const float*)d_in[i];
    }
    float* out = (float*)d_out;

    cudaFuncSetAttribute(hgc_gemm, cudaFuncAttributeMaxDynamicSharedMemorySize, SMEM_TOTAL);

    expmap_transpose<<<N_ROWS / 64, 256>>>(x);
    hgc_gemm<<<N_ROWS / 128, 256, SMEM_TOTAL>>>(adj, ker, bias, out);
}

// round 10
// speedup vs baseline: 1.2300x; 1.0406x over previous
#include <cuda_runtime.h>
#include <cstdint>

// ============================================================================
// Problem constants
// ============================================================================
static constexpr int N_ROWS = 16384;   // N nodes
static constexpr int F_DIM  = 64;      // features
static constexpr int U_DIM  = 64;      // output units

// Transposed expmap output: g_xT[n][k] = x_proj[k][n], [64, 16384] fp32 (tf32-rounded)
__device__ float g_xT[(size_t)F_DIM * N_ROWS];

// ============================================================================
// Helpers — baseline PTX only (sm_103, NO 'a'-suffix features)
// ============================================================================
__device__ __forceinline__ uint32_t smem_u32(const void* p) {
    uint32_t a;
    asm("{ .reg .u64 t; cvta.to.shared.u64 t, %1; cvt.u32.u64 %0, t; }"
        : "=r"(a) : "l"(p));
    return a;
}

// SW128 swizzle valid for 128-byte rows: XOR bits[6:4] with row&7
#define SW128(x) ((x) ^ (((x) >> 3) & 0x70))

__device__ __forceinline__ void cp_async16(uint32_t saddr, const void* gptr) {
    asm volatile("cp.async.cg.shared.global [%0], [%1], 16;"
                 :: "r"(saddr), "l"(gptr) : "memory");
}
#define CP_COMMIT() asm volatile("cp.async.commit_group;" ::: "memory")
template <int Ngrp>
__device__ __forceinline__ void cp_wait() {
    asm volatile("cp.async.wait_group %0;" :: "n"(Ngrp) : "memory");
}

__device__ __forceinline__ void ldsm_x4(uint32_t r[4], uint32_t addr) {
    asm volatile("ldmatrix.sync.aligned.m8n8.x4.shared.b16 {%0,%1,%2,%3}, [%4];"
                 : "=r"(r[0]), "=r"(r[1]), "=r"(r[2]), "=r"(r[3]) : "r"(addr));
}

__device__ __forceinline__ uint32_t cvt_rna_tf32(uint32_t x) {
    uint32_t y;
    asm("cvt.rna.tf32.f32 %0, %1;" : "=r"(y) : "f"(__uint_as_float(x)));
    return y;
}

// D += A*B, m16n8k8 tf32, fp32 accumulate (sm_80+ baseline ISA)
__device__ __forceinline__ void mma_tf32(float d[4], const uint32_t a[4],
                                         uint32_t b0, uint32_t b1) {
    asm volatile(
        "mma.sync.aligned.m16n8k8.row.col.f32.tf32.tf32.f32 "
        "{%0,%1,%2,%3}, {%4,%5,%6,%7}, {%8,%9}, {%0,%1,%2,%3};"
        : "+f"(d[0]), "+f"(d[1]), "+f"(d[2]), "+f"(d[3])
        : "r"(a[0]), "r"(a[1]), "r"(a[2]), "r"(a[3]), "r"(b0), "r"(b1));
}

// ============================================================================
// Kernel 1: Poincare expmap + transpose (x[16384,64] -> g_xT[64,16384])
// ============================================================================
__global__ __launch_bounds__(256) void expmap_transpose(const float* __restrict__ x) {
    __shared__ float tile[64][65];
    __shared__ float scl[64];
    const int k0 = blockIdx.x * 64;
    const int t = threadIdx.x;

#pragma unroll
    for (int i = 0; i < 16; i++) {
        int idx = t + i * 256;
        int r = idx >> 6, c = idx & 63;
        tile[r][c] = x[(size_t)(k0 + r) * F_DIM + c];
    }
    __syncthreads();

    if (t < 64) {
        float s = 0.0f;
#pragma unroll
        for (int c = 0; c < 64; c++) { float v = tile[t][c]; s += v * v; }
        float n = fminf(sqrtf(s), 10.0f);
        scl[t] = tanhf(n) / (n + 1e-8f);
    }
    __syncthreads();

    const int kl = t & 63;
    const int ng = t >> 6;  // 4 groups of 64 threads
#pragma unroll
    for (int nn = ng; nn < 64; nn += 4) {
        float v = tile[kl][nn] * scl[kl];
        uint32_t u;
        asm("cvt.rna.tf32.f32 %0, %1;" : "=r"(u) : "f"(v));  // pre-round B: no bias
        g_xT[(size_t)nn * N_ROWS + k0 + kl] = __uint_as_float(u);
    }
}

// ============================================================================
// Kernel 2: pipelined tf32 mma.sync GEMM (support = adj @ x_proj)
//           + fused logmap + dense(kernel) + bias epilogue
// 256 threads, 8 warps: wm(4) x wk(2) — warp tile m32 x n64 x k32(half of KC).
//   A fragments read by exactly ONE warp (no n-duplication): -25% crossbar reads.
//   The two k-half warps per SMSP have fully independent dep chains.
//   k-halves reduced in the epilogue via two C buffers.
// KC=64 per stage (two 128B-row SW128 blocks per operand), 3 stages.
// ============================================================================
static constexpr int STAGES = 3;
static constexpr int KC     = 64;                // K per stage = 2 x 128B blocks
static constexpr int ITERS  = N_ROWS / KC;       // 256

static constexpr int SMEM_BIAS   = 128;          // 256B
static constexpr int SMEM_KER    = 512;          // 16KB, [k][u] row-major
static constexpr int SMEM_STAGE0 = 17408;        // 1024-aligned
static constexpr int STAGE_BYTES = 49152;        // A 32KB + B 16KB
static constexpr int A_OFF       = 0;            // A: 16KB block per K-half
static constexpr int B_OFF       = 32768;        // B: 8KB block per K-half
static constexpr int SMEM_TOTAL  = SMEM_STAGE0 + STAGES * STAGE_BYTES;  // 164864
static constexpr int C_STRIDE    = 68;           // floats per row (16B-aligned rows)
static constexpr int C_BYTES     = 128 * C_STRIDE * 4;       // 34816
static constexpr int SMEM_C0     = SMEM_STAGE0;              // wk=0 partials
static constexpr int SMEM_C1     = SMEM_STAGE0 + C_BYTES;    // wk=1 partials

__global__ __launch_bounds__(256, 1) void hgc_gemm(
    const float* __restrict__ adj,
    const float* __restrict__ ker,
    const float* __restrict__ bias,
    float* __restrict__ out)
{
    extern __shared__ char smem[];
    const uint32_t sb = smem_u32(smem);
    const int tid  = threadIdx.x;
    const int lane = tid & 31;
    const int wid  = tid >> 5;
    const int wm   = wid & 3;       // 4 warps along M (32 rows each)
    const int wk   = wid >> 2;      // 2 warps along K (32 of KC=64 each)
    const int m0   = blockIdx.x * 128;

    // stage kernel matrix + bias into smem
    float* kers = (float*)(smem + SMEM_KER);
#pragma unroll
    for (int i = 0; i < 16; i++) kers[tid + i * 256] = ker[tid + i * 256];
    if (tid < 64) ((float*)(smem + SMEM_BIAS))[tid] = bias[tid];
    __syncthreads();

    // ---- cp.async mapping: 3072 16B chunks / 256 threads = 12 each
    const char* gp[12];
    uint32_t so[12];
#pragma unroll
    for (int j = 0; j < 12; j++) {
        int c = tid + j * 256;
        if (c < 2048) {
            int r = c >> 4, cc = c & 15;
            gp[j] = (const char*)(adj + (size_t)(m0 + r) * N_ROWS) + cc * 16;
            so[j] = A_OFF + (cc >> 3) * 16384 + SW128(r * 128 + (cc & 7) * 16);
        } else {
            int c2 = c - 2048;
            int n = c2 >> 4, cc = c2 & 15;
            gp[j] = (const char*)(g_xT + (size_t)n * N_ROWS) + cc * 16;
            so[j] = B_OFF + (cc >> 3) * 8192 + SW128(n * 128 + (cc & 7) * 16);
        }
    }

    // ---- ldmatrix swizzled offsets, fully precomputed (per lane, k8 0..3 in half)
    const int rr = lane & 7, mi = lane >> 3;
    uint32_t aOff[2][4], bOff[4][4];
    {
        const int aKhalf = (mi >> 1) * 16;
        const int bKhalf = (mi & 1) * 16;
        const int hA = wk * 16384, hB = wk * 8192;   // this warp's K-half block
#pragma unroll
        for (int k8 = 0; k8 < 4; k8++) {
            const int kin = k8 * 32;
#pragma unroll
            for (int mt = 0; mt < 2; mt++) {
                const int ar = wm * 32 + mt * 16 + (mi & 1) * 8 + rr;
                aOff[mt][k8] = A_OFF + hA + SW128(ar * 128 + kin + aKhalf);
            }
#pragma unroll
            for (int g = 0; g < 4; g++) {           // n64 = 4 groups of n16
                const int bn = g * 16 + (mi >> 1) * 8 + rr;
                bOff[g][k8] = B_OFF + hB + SW128(bn * 128 + kin + bKhalf);
            }
        }
    }

    float acc[2][8][4];
#pragma unroll
    for (int mt = 0; mt < 2; mt++)
#pragma unroll
        for (int nt = 0; nt < 8; nt++)
#pragma unroll
            for (int q = 0; q < 4; q++) acc[mt][nt][q] = 0.0f;

    // ---- prologue: fill stages 0..1
#pragma unroll 1
    for (int s = 0; s < STAGES - 1; s++) {
        const uint32_t stb = sb + SMEM_STAGE0 + s * STAGE_BYTES;
        const size_t goff = (size_t)s * 256;  // KC*4 bytes along K
#pragma unroll
        for (int j = 0; j < 12; j++) cp_async16(stb + so[j], gp[j] + goff);
        CP_COMMIT();
    }

    // ---- main loop (256 iterations, one barrier each)
#pragma unroll 1
    for (int i = 0; i < ITERS; i++) {
        cp_wait<STAGES - 2>();     // stage i landed
        __syncthreads();           // visible to all; slot (i+2)%3 free to refill

        const int nx = i + STAGES - 1;
        if (nx < ITERS) {
            const uint32_t stb = sb + SMEM_STAGE0 + (nx % STAGES) * STAGE_BYTES;
            const size_t goff = (size_t)nx * 256;
#pragma unroll
            for (int j = 0; j < 12; j++) cp_async16(stb + so[j], gp[j] + goff);
        }
        CP_COMMIT();               // keep group count uniform

        const uint32_t st = sb + SMEM_STAGE0 + (i % STAGES) * STAGE_BYTES;

        // software pipeline over this warp's 4 k8 steps: double-buffered frags
        uint32_t a[2][2][4], b[2][4][4];
        ldsm_x4(a[0][0], st + aOff[0][0]);
        ldsm_x4(a[0][1], st + aOff[1][0]);
#pragma unroll
        for (int g = 0; g < 4; g++) ldsm_x4(b[0][g], st + bOff[g][0]);
#pragma unroll
        for (int k8 = 0; k8 < 4; k8++) {
            const int cur = k8 & 1, nxt = cur ^ 1;
            if (k8 < 3) {
                ldsm_x4(a[nxt][0], st + aOff[0][k8 + 1]);
                ldsm_x4(a[nxt][1], st + aOff[1][k8 + 1]);
#pragma unroll
                for (int g = 0; g < 4; g++) ldsm_x4(b[nxt][g], st + bOff[g][k8 + 1]);
            }
            uint32_t ar2[2][4];
#pragma unroll
            for (int mt = 0; mt < 2; mt++)
#pragma unroll
                for (int q = 0; q < 4; q++) ar2[mt][q] = cvt_rna_tf32(a[cur][mt][q]);
#pragma unroll
            for (int mt = 0; mt < 2; mt++)
#pragma unroll
                for (int nt = 0; nt < 8; nt++)
                    mma_tf32(acc[mt][nt], ar2[mt], b[cur][nt >> 1][(nt & 1) * 2],
                             b[cur][nt >> 1][(nt & 1) * 2 + 1]);
        }
    }
    __syncthreads();  // all compute done; stage ring reusable as C buffers

    // ---- spill partial accumulators: wk=0 -> C0, wk=1 -> C1
    float* Csm = (float*)(smem + (wk ? SMEM_C1 : SMEM_C0));
#pragma unroll
    for (int mt = 0; mt < 2; mt++) {
        const int R0 = wm * 32 + mt * 16 + (lane >> 2);
#pragma unroll
        for (int nt = 0; nt < 8; nt++) {
            const int C0 = nt * 8 + (lane & 3) * 2;
            Csm[R0 * C_STRIDE + C0]           = acc[mt][nt][0];
            Csm[R0 * C_STRIDE + C0 + 1]       = acc[mt][nt][1];
            Csm[(R0 + 8) * C_STRIDE + C0]     = acc[mt][nt][2];
            Csm[(R0 + 8) * C_STRIDE + C0 + 1] = acc[mt][nt][3];
        }
    }
    __syncthreads();

    // ---- fused epilogue: k-reduce + logmap + dense + bias (1 thread per row)
    if (tid < 128) {
        float y[64];
        const float4* c0 = (const float4*)((float*)(smem + SMEM_C0) + tid * C_STRIDE);
        const float4* c1 = (const float4*)((float*)(smem + SMEM_C1) + tid * C_STRIDE);
#pragma unroll
        for (int j = 0; j < 16; j++) {
            float4 p = c0[j], q = c1[j];
            ((float4*)y)[j] = make_float4(p.x + q.x, p.y + q.y, p.z + q.z, p.w + q.w);
        }

        float s2 = 0.0f;
#pragma unroll
        for (int j = 0; j < 64; j++) s2 += y[j] * y[j];
        float nrm = sqrtf(s2);
        float nc = fminf(nrm, 0.999f);
        float sc = atanhf(nc) / (nc + 1e-8f);
#pragma unroll
        for (int j = 0; j < 64; j++) y[j] *= sc;

        const float4* kf = (const float4*)(smem + SMEM_KER);   // [k][u]
        const float* bs = (const float*)(smem + SMEM_BIAS);
        float4* outv = (float4*)(out + (size_t)(m0 + tid) * U_DIM);
#pragma unroll 1
        for (int u0 = 0; u0 < 16; u0++) {
            float4 a4 = make_float4(bs[u0 * 4], bs[u0 * 4 + 1],
                                    bs[u0 * 4 + 2], bs[u0 * 4 + 3]);
#pragma unroll
            for (int k = 0; k < 64; k++) {
                float4 kv = kf[k * 16 + u0];   // broadcast LDS128
                a4.x += y[k] * kv.x; a4.y += y[k] * kv.y;
                a4.z += y[k] * kv.z; a4.w += y[k] * kv.w;
            }
            outv[u0] = a4;
        }
    }
}

// ============================================================================
// Launch
// ============================================================================
extern "C" void kernel_launch(void* const* d_in, const int* in_sizes, int n_in,
                              void* d_out, int out_size) {
    const float *x = nullptr, *adj = nullptr, *ker = nullptr, *bias = nullptr;
    for (int i = 0; i < n_in; i++) {
        long sz = in_sizes[i];
        if (sz == (long)N_ROWS * N_ROWS)      adj  = (const float*)d_in[i];
        else if (sz == (long)N_ROWS * F_DIM)  x    = (const float*)d_in[i];
        else if (sz == (long)F_DIM * U_DIM)   ker  = (const float*)d_in[i];
        else if (sz == (long)U_DIM)           bias = (const float*)d_in[i];
    }
    float* out = (float*)d_out;

    cudaFuncSetAttribute(hgc_gemm, cudaFuncAttributeMaxDynamicSharedMemorySize, SMEM_TOTAL);

    expmap_transpose<<<N_ROWS / 64, 256>>>(x);
    hgc_gemm<<<N_ROWS / 128, 256, SMEM_TOTAL>>>(adj, ker, bias, out);
}